// round 3
// baseline (speedup 1.0000x reference)
#include <cuda_runtime.h>
#include <math.h>

#define NSAMP 2048
#define DIM   512
#define NCLS  100
#define SHRINK 1e-4f

// ---------------- scratch (device globals; no runtime allocation) ----------------
__device__ float g_M[NCLS * DIM * DIM];                 // M_c -> becomes Lambda_c in place
__device__ float g_v[NCLS * DIM];                       // v_c = Lambda_c mu_c
__device__ float g_frob2[NCLS];                         // ||RegSigma_c||_F^2
__device__ float g_const[NCLS];                         // log prior - 0.25*log(frob2) - 0.5*gamma

// ---------------- kernel 1: build M_c ----------------
// grid (DIM, NCLS), block 128: one row per block, float4 per thread
__global__ void build_kernel(const float* __restrict__ SigK, const float* __restrict__ Sig) {
    int d = blockIdx.x, c = blockIdx.y;
    size_t base = ((size_t)c * DIM + d) * DIM;
    const float4* skr = (const float4*)(SigK + base);
    const float4* sgr = (const float4*)(Sig + (size_t)d * DIM);
    float4* mr = (float4*)(g_M + base);
    int t = threadIdx.x;                     // 128 threads, 128 float4 = 512 floats
    float4 a = skr[t], b = sgr[t];
    const float w = 0.5f * (1.0f - SHRINK);
    float4 o;
    o.x = w * (a.x + b.x);
    o.y = w * (a.y + b.y);
    o.z = w * (a.z + b.z);
    o.w = w * (a.w + b.w);
    int e0 = t * 4;
    if (d >= e0 && d < e0 + 4) {
        if (d == e0 + 0) o.x += SHRINK;
        if (d == e0 + 1) o.y += SHRINK;
        if (d == e0 + 2) o.z += SHRINK;
        if (d == e0 + 3) o.w += SHRINK;
    }
    mr[t] = o;
}

// ---------------- kernel 2: deterministic Frobenius^2 of RegSigma ----------------
__global__ void frob_kernel(const float* __restrict__ SigK, const float* __restrict__ Sig) {
    int c = blockIdx.x;
    const float* sk = SigK + (size_t)c * DIM * DIM;
    float acc = 0.f;
    for (int i = threadIdx.x; i < DIM * DIM; i += 256) {
        float r = 0.5f * sk[i] + 0.5f * Sig[i];
        acc += r * r;
    }
    __shared__ float red[256];
    red[threadIdx.x] = acc;
    __syncthreads();
    for (int s = 128; s > 0; s >>= 1) {
        if (threadIdx.x < s) red[threadIdx.x] += red[threadIdx.x + s];
        __syncthreads();
    }
    if (threadIdx.x == 0) g_frob2[c] = red[0];
}

// ---------------- kernel 3: batched in-place inversion (blocked Gauss-Jordan sweep) ----
// One CTA (256 threads) per matrix. Block size 64, 8 passes.
// Per pass K: Pi = inv(M[K][K]); row: M[K][J] = Pi@old; trail: M[I][J] -= oldcol@newrow;
// col: M[I][K] = -oldcol@Pi; M[K][K] = Pi.   (block sweep operator; exact fp32 direct method)
__global__ __launch_bounds__(256) void invert_kernel() {
    const int c = blockIdx.x;
    float* M = g_M + (size_t)c * DIM * DIM;
    __shared__ float P[64][64];   // pivot block inverse
    __shared__ float Rt[64][64];  // row block (rows 0/1 reused as rowk/colk during pivot GJ)
    __shared__ float Cs[64][64];  // column block, swizzled: (k,i) stored at Cs[k][(i+k)&63]
    float* rowk = &Rt[0][0];
    float* colk = &Rt[1][0];
    const int tid = threadIdx.x;
    const int tx = tid & 15, ty = tid >> 4;
    const int i0 = ty * 4, j0 = tx * 4;

    for (int K = 0; K < 8; ++K) {
        const int K0 = K * 64;
        // --- load pivot block
        for (int idx = tid; idx < 64 * 64; idx += 256) {
            int i = idx >> 6, j = idx & 63;
            P[i][j] = M[(size_t)(K0 + i) * DIM + K0 + j];
        }
        __syncthreads();
        // --- unblocked GJ inversion of P (SPD pivot: no pivoting needed)
        for (int k = 0; k < 64; ++k) {
            if (tid < 64) { rowk[tid] = P[k][tid]; colk[tid] = P[tid][k]; }
            __syncthreads();
            float ipiv = 1.0f / rowk[k];
            for (int idx = tid; idx < 64 * 64; idx += 256) {
                int i = idx >> 6, j = idx & 63;
                float v;
                if (i == k)      v = (j == k) ? ipiv : rowk[j] * ipiv;
                else if (j == k) v = -colk[i] * ipiv;
                else             v = P[i][j] - colk[i] * ipiv * rowk[j];
                P[i][j] = v;
            }
            __syncthreads();
        }
        // --- row block update: M[K][J] = P @ oldRow
        for (int J = 0; J < 8; ++J) {
            if (J == K) continue;
            const int J0 = J * 64;
            for (int idx = tid; idx < 64 * 64; idx += 256) {
                int k = idx >> 6, j = idx & 63;
                Rt[k][j] = M[(size_t)(K0 + k) * DIM + J0 + j];
            }
            __syncthreads();
            float acc[4][4] = {};
            #pragma unroll 8
            for (int k = 0; k < 64; ++k) {
                float a0 = P[i0][k], a1 = P[i0 + 1][k], a2 = P[i0 + 2][k], a3 = P[i0 + 3][k];
                float4 b = *(float4*)&Rt[k][j0];
                acc[0][0] += a0 * b.x; acc[0][1] += a0 * b.y; acc[0][2] += a0 * b.z; acc[0][3] += a0 * b.w;
                acc[1][0] += a1 * b.x; acc[1][1] += a1 * b.y; acc[1][2] += a1 * b.z; acc[1][3] += a1 * b.w;
                acc[2][0] += a2 * b.x; acc[2][1] += a2 * b.y; acc[2][2] += a2 * b.z; acc[2][3] += a2 * b.w;
                acc[3][0] += a3 * b.x; acc[3][1] += a3 * b.y; acc[3][2] += a3 * b.z; acc[3][3] += a3 * b.w;
            }
            #pragma unroll
            for (int ii = 0; ii < 4; ++ii)
                *(float4*)&M[(size_t)(K0 + i0 + ii) * DIM + J0 + j0] = make_float4(acc[ii][0], acc[ii][1], acc[ii][2], acc[ii][3]);
            __syncthreads();
        }
        // --- trailing + column updates (per old column block I)
        for (int I = 0; I < 8; ++I) {
            if (I == K) continue;
            const int I0 = I * 64;
            // load old column block, transposed + swizzled (coalesced global, conflict-free smem)
            for (int idx = tid; idx < 64 * 64; idx += 256) {
                int i = idx >> 6, k = idx & 63;
                Cs[k][(i + k) & 63] = M[(size_t)(I0 + i) * DIM + K0 + k];
            }
            __syncthreads();
            for (int J = 0; J < 8; ++J) {
                if (J == K) continue;
                const int J0 = J * 64;
                for (int idx = tid; idx < 64 * 64; idx += 256) {
                    int k = idx >> 6, j = idx & 63;
                    Rt[k][j] = M[(size_t)(K0 + k) * DIM + J0 + j];   // NEW row block
                }
                __syncthreads();
                float acc[4][4] = {};
                #pragma unroll 8
                for (int k = 0; k < 64; ++k) {
                    float a0 = Cs[k][(i0 + 0 + k) & 63];
                    float a1 = Cs[k][(i0 + 1 + k) & 63];
                    float a2 = Cs[k][(i0 + 2 + k) & 63];
                    float a3 = Cs[k][(i0 + 3 + k) & 63];
                    float4 b = *(float4*)&Rt[k][j0];
                    acc[0][0] += a0 * b.x; acc[0][1] += a0 * b.y; acc[0][2] += a0 * b.z; acc[0][3] += a0 * b.w;
                    acc[1][0] += a1 * b.x; acc[1][1] += a1 * b.y; acc[1][2] += a1 * b.z; acc[1][3] += a1 * b.w;
                    acc[2][0] += a2 * b.x; acc[2][1] += a2 * b.y; acc[2][2] += a2 * b.z; acc[2][3] += a2 * b.w;
                    acc[3][0] += a3 * b.x; acc[3][1] += a3 * b.y; acc[3][2] += a3 * b.z; acc[3][3] += a3 * b.w;
                }
                #pragma unroll
                for (int ii = 0; ii < 4; ++ii) {
                    float4* p = (float4*)&M[(size_t)(I0 + i0 + ii) * DIM + J0 + j0];
                    float4 o = *p;
                    o.x -= acc[ii][0]; o.y -= acc[ii][1]; o.z -= acc[ii][2]; o.w -= acc[ii][3];
                    *p = o;
                }
                __syncthreads();
            }
            // column update: M[I][K] = -oldCol @ P  (oldCol is in Cs)
            float acc[4][4] = {};
            #pragma unroll 8
            for (int k = 0; k < 64; ++k) {
                float a0 = Cs[k][(i0 + 0 + k) & 63];
                float a1 = Cs[k][(i0 + 1 + k) & 63];
                float a2 = Cs[k][(i0 + 2 + k) & 63];
                float a3 = Cs[k][(i0 + 3 + k) & 63];
                float4 b = *(float4*)&P[k][j0];
                acc[0][0] += a0 * b.x; acc[0][1] += a0 * b.y; acc[0][2] += a0 * b.z; acc[0][3] += a0 * b.w;
                acc[1][0] += a1 * b.x; acc[1][1] += a1 * b.y; acc[1][2] += a1 * b.z; acc[1][3] += a1 * b.w;
                acc[2][0] += a2 * b.x; acc[2][1] += a2 * b.y; acc[2][2] += a2 * b.z; acc[2][3] += a2 * b.w;
                acc[3][0] += a3 * b.x; acc[3][1] += a3 * b.y; acc[3][2] += a3 * b.z; acc[3][3] += a3 * b.w;
            }
            #pragma unroll
            for (int ii = 0; ii < 4; ++ii)
                *(float4*)&M[(size_t)(I0 + i0 + ii) * DIM + K0 + j0] = make_float4(-acc[ii][0], -acc[ii][1], -acc[ii][2], -acc[ii][3]);
            __syncthreads();
        }
        // --- pivot block <- P
        for (int idx = tid; idx < 64 * 64; idx += 256) {
            int i = idx >> 6, j = idx & 63;
            M[(size_t)(K0 + i) * DIM + K0 + j] = P[i][j];
        }
        __syncthreads();
    }
}

// ---------------- kernel 4: v_c = Lambda_c mu_c, gamma, score constant ----------------
__global__ __launch_bounds__(512) void vgamma_kernel(const float* __restrict__ muK,
                                                     const float* __restrict__ cK) {
    int c = blockIdx.x;
    const float* L = g_M + (size_t)c * DIM * DIM;
    const float* mu = muK + (size_t)c * DIM;
    __shared__ float mus[DIM];
    __shared__ float vs[DIM];
    __shared__ float red[DIM];
    int tid = threadIdx.x;
    mus[tid] = mu[tid];
    __syncthreads();
    int warp = tid >> 5, lane = tid & 31;
    for (int r = 0; r < 32; ++r) {
        int d = warp * 32 + r;
        float a = 0.f;
        const float* row = L + (size_t)d * DIM;
        for (int e = lane; e < DIM; e += 32) a += row[e] * mus[e];
        for (int o = 16; o > 0; o >>= 1) a += __shfl_xor_sync(0xffffffffu, a, o);
        if (lane == 0) vs[d] = a;
    }
    __syncthreads();
    g_v[(size_t)c * DIM + tid] = vs[tid];
    red[tid] = vs[tid] * mus[tid];
    __syncthreads();
    for (int s = 256; s > 0; s >>= 1) {
        if (tid < s) red[tid] += red[tid + s];
        __syncthreads();
    }
    if (tid == 0) {
        float ssum = 0.f;
        for (int k = 0; k < NCLS; ++k) ssum += cK[k];
        float ck = cK[c];
        float cst;
        if (ck == 0.f) cst = -INFINITY;
        else cst = logf(ck / ssum) - 0.25f * logf(g_frob2[c]) - 0.5f * red[0];
        g_const[c] = cst;
    }
}

// ---------------- kernel 5: fused batched GEMM + score ----------------
// grid (NSAMP/128, NCLS), 256 threads. Each CTA owns a 128-sample strip for one class.
// Loops over 4 d-tiles of 128: computes W-tile = X_tile @ Lambda[:, d-tile] in registers
// (128x128x16 smem tiling, 8x8 microtile), then contracts immediately:
//   sc[n] += sum_j X[n][d0+j] * (v_c[d0+j] - 0.5 * W[n][d0+j])
// Final: out[n,c] = g_const[c] + sc[n]. No W materialization.
__global__ __launch_bounds__(256) void quad_score(const float* __restrict__ X,
                                                  float* __restrict__ out) {
    int c = blockIdx.y;
    int n0 = blockIdx.x * 128;
    const float* B = g_M + (size_t)c * DIM * DIM;
    const float* v = g_v + (size_t)c * DIM;
    __shared__ float As[16][132];   // As[k][i] = X[n0+i][k0+k]
    __shared__ float Bs[16][132];   // Bs[k][j] = Lambda[k0+k][d0+j]
    int tid = threadIdx.x;
    int tx = tid & 15, ty = tid >> 4;
    float sc[8] = {};

    for (int dt = 0; dt < 4; ++dt) {
        const int d0 = dt * 128;
        float acc[8][8] = {};
        for (int k0 = 0; k0 < DIM; k0 += 16) {
            for (int t = tid; t < 512; t += 256) {
                int row = t >> 2;
                int kq = (t & 3) * 4;
                float4 vv = *(const float4*)&X[(size_t)(n0 + row) * DIM + k0 + kq];
                As[kq + 0][row] = vv.x; As[kq + 1][row] = vv.y;
                As[kq + 2][row] = vv.z; As[kq + 3][row] = vv.w;
            }
            for (int t = tid; t < 512; t += 256) {
                int kr = t >> 5;
                int jq = (t & 31) * 4;
                *(float4*)&Bs[kr][jq] = *(const float4*)&B[(size_t)(k0 + kr) * DIM + d0 + jq];
            }
            __syncthreads();
            #pragma unroll
            for (int k = 0; k < 16; ++k) {
                float4 a0 = *(float4*)&As[k][ty * 4];
                float4 a1 = *(float4*)&As[k][64 + ty * 4];
                float4 b0 = *(float4*)&Bs[k][tx * 4];
                float4 b1 = *(float4*)&Bs[k][64 + tx * 4];
                float a[8] = {a0.x, a0.y, a0.z, a0.w, a1.x, a1.y, a1.z, a1.w};
                float b[8] = {b0.x, b0.y, b0.z, b0.w, b1.x, b1.y, b1.z, b1.w};
                #pragma unroll
                for (int i = 0; i < 8; ++i)
                    #pragma unroll
                    for (int j = 0; j < 8; ++j)
                        acc[i][j] += a[i] * b[j];
            }
            __syncthreads();
        }
        // epilogue contraction: sc[i] += sum_j X[n_i][d_j] * (v[d_j] - 0.5*acc[i][j])
        float4 v0 = *(const float4*)&v[d0 + tx * 4];
        float4 v1 = *(const float4*)&v[d0 + 64 + tx * 4];
        float vr[8] = {v0.x, v0.y, v0.z, v0.w, v1.x, v1.y, v1.z, v1.w};
        #pragma unroll
        for (int i = 0; i < 8; ++i) {
            int gi = n0 + ((i < 4) ? (ty * 4 + i) : (64 + ty * 4 + i - 4));
            const float* xr = X + (size_t)gi * DIM + d0;
            float4 x0 = *(const float4*)&xr[tx * 4];
            float4 x1 = *(const float4*)&xr[64 + tx * 4];
            float xrv[8] = {x0.x, x0.y, x0.z, x0.w, x1.x, x1.y, x1.z, x1.w};
            float s = 0.f;
            #pragma unroll
            for (int j = 0; j < 8; ++j)
                s += xrv[j] * (vr[j] - 0.5f * acc[i][j]);
            sc[i] += s;
        }
    }
    // reduce sc[i] across the 16 tx lanes (tid = ty*16+tx; lane = (ty&1)*16+tx,
    // so xor offsets 8,4,2,1 stay inside the 16-lane tx group)
    #pragma unroll
    for (int i = 0; i < 8; ++i) {
        float s = sc[i];
        #pragma unroll
        for (int o = 8; o > 0; o >>= 1) s += __shfl_xor_sync(0xffffffffu, s, o);
        sc[i] = s;
    }
    if (tx == 0) {
        float cst = g_const[c];
        #pragma unroll
        for (int i = 0; i < 8; ++i) {
            int gi = n0 + ((i < 4) ? (ty * 4 + i) : (64 + ty * 4 + i - 4));
            out[(size_t)gi * NCLS + c] = cst + sc[i];
        }
    }
}

// ---------------- launch ----------------
extern "C" void kernel_launch(void* const* d_in, const int* in_sizes, int n_in,
                              void* d_out, int out_size) {
    const float* X    = (const float*)d_in[0];   // [2048, 512]
    const float* muK  = (const float*)d_in[1];   // [100, 512]
    const float* SigK = (const float*)d_in[2];   // [100, 512, 512]
    const float* Sig  = (const float*)d_in[3];   // [512, 512]
    const float* cK   = (const float*)d_in[4];   // [100]
    float* out = (float*)d_out;                  // [2048, 100]

    build_kernel<<<dim3(DIM, NCLS), 128>>>(SigK, Sig);
    frob_kernel<<<NCLS, 256>>>(SigK, Sig);
    invert_kernel<<<NCLS, 256>>>();
    vgamma_kernel<<<NCLS, 512>>>(muK, cK);
    quad_score<<<dim3(NSAMP / 128, NCLS), 256>>>(X, out);
}

// round 12
// speedup vs baseline: 1.6609x; 1.6609x over previous
#include <cuda_runtime.h>
#include <cuda_bf16.h>
#include <math.h>
#include <stdint.h>

#define NSAMP 2048
#define DIM   512
#define NCLS  100
#define SHRINK 1e-4f

// ================= scratch (device globals; no runtime allocation) =================
__device__ float g_M[NCLS * DIM * DIM];                 // M_c -> becomes Lambda_c in place
__device__ float g_v[NCLS * DIM];                       // v_c = Lambda_c mu_c
__device__ float g_frob2[NCLS];                         // ||RegSigma_c||_F^2
__device__ float g_const[NCLS];                         // log prior - 0.25*log(frob2) - 0.5*gamma

// bf16 operands, stored PRE-SWIZZLED (SW128) as [tile][128B rows]
// X tiles: per (rowblock rb of 16, kchunk kc of 8): 128 rows x 64 cols bf16 (16KB). hi + lo split.
__device__ __align__(1024) __nv_bfloat16 g_Xh[16 * 8 * 128 * 64];
__device__ __align__(1024) __nv_bfloat16 g_Xl[16 * 8 * 128 * 64];
// L tiles: per (class c, kchunk kc of 8): 512 rows x 64 cols bf16 (64KB). single bf16 (rn).
__device__ __align__(1024) __nv_bfloat16 g_Lb[NCLS * 8 * 512 * 64];

// ================= PTX helpers =================
__device__ __forceinline__ uint32_t smem_u32(const void* p) {
    uint32_t a;
    asm("{ .reg .u64 t; cvta.to.shared.u64 t, %1; cvt.u32.u64 %0, t; }" : "=r"(a) : "l"(p));
    return a;
}
#define MBAR_INIT(addr, cnt) \
    asm volatile("mbarrier.init.shared.b64 [%0], %1;" :: "r"(addr), "r"(cnt) : "memory")
#define MBAR_EXPECT_TX(addr, bytes) \
    asm volatile("mbarrier.arrive.expect_tx.shared.b64 _, [%0], %1;" :: "r"(addr), "r"(bytes) : "memory")
#define MBAR_WAIT(addr, parity) do {                                             \
    asm volatile("{\n\t.reg .pred P1;\n\t"                                       \
        "WAIT_LP_%=:\n\t"                                                        \
        "mbarrier.try_wait.parity.shared.b64 P1, [%0], %1;\n\t"                  \
        "@P1 bra.uni WAIT_DN_%=;\n\t"                                            \
        "bra.uni WAIT_LP_%=;\n\t"                                                \
        "WAIT_DN_%=:\n\t}"                                                       \
        :: "r"(addr), "r"(parity) : "memory");                                   \
} while (0)
#define BULK_G2S(dst, src, bytes, mbar) \
    asm volatile("cp.async.bulk.shared::cta.global.mbarrier::complete_tx::bytes [%0], [%1], %2, [%3];" \
        :: "r"(dst), "l"(src), "r"(bytes), "r"(mbar) : "memory")
#define LDSM_X4(r, addr) \
    asm volatile("ldmatrix.sync.aligned.m8n8.x4.shared.b16 {%0,%1,%2,%3}, [%4];" \
        : "=r"((r)[0]), "=r"((r)[1]), "=r"((r)[2]), "=r"((r)[3]) : "r"(addr))
#define MMA_BF16(d, a, b0, b1) \
    asm volatile("mma.sync.aligned.m16n8k16.row.col.f32.bf16.bf16.f32 " \
        "{%0,%1,%2,%3}, {%4,%5,%6,%7}, {%8,%9}, {%0,%1,%2,%3};" \
        : "+f"((d)[0]), "+f"((d)[1]), "+f"((d)[2]), "+f"((d)[3]) \
        : "r"((a)[0]), "r"((a)[1]), "r"((a)[2]), "r"((a)[3]), "r"(b0), "r"(b1))

__device__ __forceinline__ uint32_t swz128(uint32_t byte_off) {
    return byte_off ^ ((byte_off >> 3) & 0x70);
}

// ================= kernel 1: build M_c =================
__global__ void build_kernel(const float* __restrict__ SigK, const float* __restrict__ Sig) {
    int d = blockIdx.x, c = blockIdx.y;
    size_t base = ((size_t)c * DIM + d) * DIM;
    const float4* skr = (const float4*)(SigK + base);
    const float4* sgr = (const float4*)(Sig + (size_t)d * DIM);
    float4* mr = (float4*)(g_M + base);
    int t = threadIdx.x;
    float4 a = skr[t], b = sgr[t];
    const float w = 0.5f * (1.0f - SHRINK);
    float4 o;
    o.x = w * (a.x + b.x);
    o.y = w * (a.y + b.y);
    o.z = w * (a.z + b.z);
    o.w = w * (a.w + b.w);
    int e0 = t * 4;
    if (d >= e0 && d < e0 + 4) {
        if (d == e0 + 0) o.x += SHRINK;
        if (d == e0 + 1) o.y += SHRINK;
        if (d == e0 + 2) o.z += SHRINK;
        if (d == e0 + 3) o.w += SHRINK;
    }
    mr[t] = o;
}

// ================= kernel 2: Frobenius^2 =================
__global__ void frob_kernel(const float* __restrict__ SigK, const float* __restrict__ Sig) {
    int c = blockIdx.x;
    const float* sk = SigK + (size_t)c * DIM * DIM;
    float acc = 0.f;
    for (int i = threadIdx.x; i < DIM * DIM; i += 256) {
        float r = 0.5f * sk[i] + 0.5f * Sig[i];
        acc += r * r;
    }
    __shared__ float red[256];
    red[threadIdx.x] = acc;
    __syncthreads();
    for (int s = 128; s > 0; s >>= 1) {
        if (threadIdx.x < s) red[threadIdx.x] += red[threadIdx.x + s];
        __syncthreads();
    }
    if (threadIdx.x == 0) g_frob2[c] = red[0];
}

// ================= kernel 3: batched in-place blocked Gauss-Jordan inversion =================
__global__ __launch_bounds__(256) void invert_kernel() {
    const int c = blockIdx.x;
    float* M = g_M + (size_t)c * DIM * DIM;
    __shared__ float P[64][64];
    __shared__ float Rt[64][64];
    __shared__ float Cs[64][64];
    float* rowk = &Rt[0][0];
    float* colk = &Rt[1][0];
    const int tid = threadIdx.x;
    const int tx = tid & 15, ty = tid >> 4;
    const int i0 = ty * 4, j0 = tx * 4;

    for (int K = 0; K < 8; ++K) {
        const int K0 = K * 64;
        for (int idx = tid; idx < 64 * 64; idx += 256) {
            int i = idx >> 6, j = idx & 63;
            P[i][j] = M[(size_t)(K0 + i) * DIM + K0 + j];
        }
        __syncthreads();
        for (int k = 0; k < 64; ++k) {
            if (tid < 64) { rowk[tid] = P[k][tid]; colk[tid] = P[tid][k]; }
            __syncthreads();
            float ipiv = 1.0f / rowk[k];
            for (int idx = tid; idx < 64 * 64; idx += 256) {
                int i = idx >> 6, j = idx & 63;
                float v;
                if (i == k)      v = (j == k) ? ipiv : rowk[j] * ipiv;
                else if (j == k) v = -colk[i] * ipiv;
                else             v = P[i][j] - colk[i] * ipiv * rowk[j];
                P[i][j] = v;
            }
            __syncthreads();
        }
        for (int J = 0; J < 8; ++J) {
            if (J == K) continue;
            const int J0 = J * 64;
            for (int idx = tid; idx < 64 * 64; idx += 256) {
                int k = idx >> 6, j = idx & 63;
                Rt[k][j] = M[(size_t)(K0 + k) * DIM + J0 + j];
            }
            __syncthreads();
            float acc[4][4] = {};
            #pragma unroll 8
            for (int k = 0; k < 64; ++k) {
                float a0 = P[i0][k], a1 = P[i0 + 1][k], a2 = P[i0 + 2][k], a3 = P[i0 + 3][k];
                float4 b = *(float4*)&Rt[k][j0];
                acc[0][0] += a0 * b.x; acc[0][1] += a0 * b.y; acc[0][2] += a0 * b.z; acc[0][3] += a0 * b.w;
                acc[1][0] += a1 * b.x; acc[1][1] += a1 * b.y; acc[1][2] += a1 * b.z; acc[1][3] += a1 * b.w;
                acc[2][0] += a2 * b.x; acc[2][1] += a2 * b.y; acc[2][2] += a2 * b.z; acc[2][3] += a2 * b.w;
                acc[3][0] += a3 * b.x; acc[3][1] += a3 * b.y; acc[3][2] += a3 * b.z; acc[3][3] += a3 * b.w;
            }
            #pragma unroll
            for (int ii = 0; ii < 4; ++ii)
                *(float4*)&M[(size_t)(K0 + i0 + ii) * DIM + J0 + j0] = make_float4(acc[ii][0], acc[ii][1], acc[ii][2], acc[ii][3]);
            __syncthreads();
        }
        for (int I = 0; I < 8; ++I) {
            if (I == K) continue;
            const int I0 = I * 64;
            for (int idx = tid; idx < 64 * 64; idx += 256) {
                int i = idx >> 6, k = idx & 63;
                Cs[k][(i + k) & 63] = M[(size_t)(I0 + i) * DIM + K0 + k];
            }
            __syncthreads();
            for (int J = 0; J < 8; ++J) {
                if (J == K) continue;
                const int J0 = J * 64;
                for (int idx = tid; idx < 64 * 64; idx += 256) {
                    int k = idx >> 6, j = idx & 63;
                    Rt[k][j] = M[(size_t)(K0 + k) * DIM + J0 + j];
                }
                __syncthreads();
                float acc[4][4] = {};
                #pragma unroll 8
                for (int k = 0; k < 64; ++k) {
                    float a0 = Cs[k][(i0 + 0 + k) & 63];
                    float a1 = Cs[k][(i0 + 1 + k) & 63];
                    float a2 = Cs[k][(i0 + 2 + k) & 63];
                    float a3 = Cs[k][(i0 + 3 + k) & 63];
                    float4 b = *(float4*)&Rt[k][j0];
                    acc[0][0] += a0 * b.x; acc[0][1] += a0 * b.y; acc[0][2] += a0 * b.z; acc[0][3] += a0 * b.w;
                    acc[1][0] += a1 * b.x; acc[1][1] += a1 * b.y; acc[1][2] += a1 * b.z; acc[1][3] += a1 * b.w;
                    acc[2][0] += a2 * b.x; acc[2][1] += a2 * b.y; acc[2][2] += a2 * b.z; acc[2][3] += a2 * b.w;
                    acc[3][0] += a3 * b.x; acc[3][1] += a3 * b.y; acc[3][2] += a3 * b.z; acc[3][3] += a3 * b.w;
                }
                #pragma unroll
                for (int ii = 0; ii < 4; ++ii) {
                    float4* p = (float4*)&M[(size_t)(I0 + i0 + ii) * DIM + J0 + j0];
                    float4 o = *p;
                    o.x -= acc[ii][0]; o.y -= acc[ii][1]; o.z -= acc[ii][2]; o.w -= acc[ii][3];
                    *p = o;
                }
                __syncthreads();
            }
            float acc[4][4] = {};
            #pragma unroll 8
            for (int k = 0; k < 64; ++k) {
                float a0 = Cs[k][(i0 + 0 + k) & 63];
                float a1 = Cs[k][(i0 + 1 + k) & 63];
                float a2 = Cs[k][(i0 + 2 + k) & 63];
                float a3 = Cs[k][(i0 + 3 + k) & 63];
                float4 b = *(float4*)&P[k][j0];
                acc[0][0] += a0 * b.x; acc[0][1] += a0 * b.y; acc[0][2] += a0 * b.z; acc[0][3] += a0 * b.w;
                acc[1][0] += a1 * b.x; acc[1][1] += a1 * b.y; acc[1][2] += a1 * b.z; acc[1][3] += a1 * b.w;
                acc[2][0] += a2 * b.x; acc[2][1] += a2 * b.y; acc[2][2] += a2 * b.z; acc[2][3] += a2 * b.w;
                acc[3][0] += a3 * b.x; acc[3][1] += a3 * b.y; acc[3][2] += a3 * b.z; acc[3][3] += a3 * b.w;
            }
            #pragma unroll
            for (int ii = 0; ii < 4; ++ii)
                *(float4*)&M[(size_t)(I0 + i0 + ii) * DIM + K0 + j0] = make_float4(-acc[ii][0], -acc[ii][1], -acc[ii][2], -acc[ii][3]);
            __syncthreads();
        }
        for (int idx = tid; idx < 64 * 64; idx += 256) {
            int i = idx >> 6, j = idx & 63;
            M[(size_t)(K0 + i) * DIM + K0 + j] = P[i][j];
        }
        __syncthreads();
    }
}

// ================= kernel 4: v_c = Lambda_c mu_c, constants =================
__global__ __launch_bounds__(512) void vgamma_kernel(const float* __restrict__ muK,
                                                     const float* __restrict__ cK) {
    int c = blockIdx.x;
    const float* L = g_M + (size_t)c * DIM * DIM;
    const float* mu = muK + (size_t)c * DIM;
    __shared__ float mus[DIM];
    __shared__ float vs[DIM];
    __shared__ float red[DIM];
    int tid = threadIdx.x;
    mus[tid] = mu[tid];
    __syncthreads();
    int warp = tid >> 5, lane = tid & 31;
    for (int r = 0; r < 32; ++r) {
        int d = warp * 32 + r;
        float a = 0.f;
        const float* row = L + (size_t)d * DIM;
        for (int e = lane; e < DIM; e += 32) a += row[e] * mus[e];
        for (int o = 16; o > 0; o >>= 1) a += __shfl_xor_sync(0xffffffffu, a, o);
        if (lane == 0) vs[d] = a;
    }
    __syncthreads();
    g_v[(size_t)c * DIM + tid] = vs[tid];
    red[tid] = vs[tid] * mus[tid];
    __syncthreads();
    for (int s = 256; s > 0; s >>= 1) {
        if (tid < s) red[tid] += red[tid + s];
        __syncthreads();
    }
    if (tid == 0) {
        float ssum = 0.f;
        for (int k = 0; k < NCLS; ++k) ssum += cK[k];
        float ck = cK[c];
        float cst;
        if (ck == 0.f) cst = -INFINITY;
        else cst = logf(ck / ssum) - 0.25f * logf(g_frob2[c]) - 0.5f * red[0];
        g_const[c] = cst;
    }
}

// ================= kernel 5a: split X into bf16 hi/lo, pre-swizzled tiles =================
__global__ void split_x_kernel(const float* __restrict__ X) {
    int rb = blockIdx.x, kc = blockIdx.y;
    size_t tile = ((size_t)(rb * 8 + kc)) * (128 * 64);
    for (int e = threadIdx.x; e < 128 * 64; e += 256) {
        int r = e >> 6, col = e & 63;
        float x = X[(size_t)(rb * 128 + r) * DIM + kc * 64 + col];
        __nv_bfloat16 hi = __float2bfloat16_rn(x);
        __nv_bfloat16 lo = __float2bfloat16_rn(x - __bfloat162float(hi));
        uint32_t sw = swz128((uint32_t)(r * 128 + col * 2));
        g_Xh[tile + (sw >> 1)] = hi;
        g_Xl[tile + (sw >> 1)] = lo;
    }
}

// ================= kernel 5b: Lambda -> bf16 (rn), pre-swizzled tiles =================
__global__ void split_l_kernel() {
    int c = blockIdx.x, kc = blockIdx.y;
    size_t tile = ((size_t)(c * 8 + kc)) * (512 * 64);
    const float* L = g_M + (size_t)c * DIM * DIM;
    for (int e = threadIdx.x; e < 512 * 64; e += 256) {
        int r = e >> 6, col = e & 63;
        float x = L[(size_t)r * DIM + kc * 64 + col];
        uint32_t sw = swz128((uint32_t)(r * 128 + col * 2));
        g_Lb[tile + (sw >> 1)] = __float2bfloat16_rn(x);
    }
}

// ================= kernel 6: HMMA quad + score =================
// grid (16 rowblocks, NCLS), 256 threads (8 warps: wm = wid&1 m64-half, wn = wid>>1 n32-quarter).
// For dt in 0..3 (d-tiles of 128): accumulate W = [Xh;Xl] @ Lb over K'=1024 via
// mma.m16n8k16 bf16, then contract tile into sc in regs. Double-buffered cp.async.bulk.
#define SM_FULL0 0
#define SM_FULL1 8
#define SM_V     128
#define SM_RED   2176
#define SM_A0    4096
#define SM_A1    20480
#define SM_B0    36864
#define SM_B1    53248
#define SM_TOTAL_Q 69632

__global__ __launch_bounds__(256) void quad_mma_kernel(const float* __restrict__ X,
                                                       float* __restrict__ out) {
    extern __shared__ char smem[];
    uint32_t sb = smem_u32(smem);
    int tid = threadIdx.x, wid = tid >> 5, lane = tid & 31;
    int rb = blockIdx.x, c = blockIdx.y;
    int wm = wid & 1, wn = wid >> 1;
    int n0 = rb * 128;
    float* vsh = (float*)(smem + SM_V);

    for (int i = tid; i < DIM; i += 256) vsh[i] = g_v[(size_t)c * DIM + i];
    if (tid == 0) {
        MBAR_INIT(sb + SM_FULL0, 1);
        MBAR_INIT(sb + SM_FULL1, 1);
    }
    __syncthreads();

    // prologue: it=0 (dt0, kc0, part h) — A + B
    if (tid == 0) {
        MBAR_EXPECT_TX(sb + SM_FULL0, 32768u);
        BULK_G2S(sb + SM_A0, g_Xh + ((size_t)(rb * 8 + 0)) * 8192, 16384u, sb + SM_FULL0);
        BULK_G2S(sb + SM_B0, g_Lb + ((size_t)(c * 8 + 0)) * 32768, 16384u, sb + SM_FULL0);
    }

    // per-lane ldmatrix addressing: row = lane&15 (+16*frag), k-half = lane>>4
    int lrow = lane & 15, lhalf = lane >> 4;
    uint32_t S = (uint32_t)((lrow & 7) << 4);                 // swizzle XOR (row&7)<<4
    uint32_t aR = (uint32_t)((wm * 64 + lrow) * 128);         // A row byte base
    uint32_t bR = (uint32_t)((wn * 32 + lrow) * 128);         // B row byte base

    float acc[4][4][4] = {};
    float scp[8] = {};

    for (int it = 0; it < 64; ++it) {
        int sA = it & 1, sB = (it >> 1) & 1;
        if (tid == 0 && it + 1 < 64) {
            int nx = it + 1;
            int dt = nx >> 4, kc = (nx >> 1) & 7, part = nx & 1;
            uint32_t fb = sb + ((nx & 1) ? SM_FULL1 : SM_FULL0);
            uint32_t ab = sb + ((nx & 1) ? SM_A1 : SM_A0);
            const __nv_bfloat16* asrc = (part ? g_Xl : g_Xh) + ((size_t)(rb * 8 + kc)) * 8192;
            if (part == 0) {
                uint32_t bb = sb + (((nx >> 1) & 1) ? SM_B1 : SM_B0);
                MBAR_EXPECT_TX(fb, 32768u);
                BULK_G2S(ab, asrc, 16384u, fb);
                BULK_G2S(bb, g_Lb + ((size_t)(c * 8 + kc)) * 32768 + dt * 8192, 16384u, fb);
            } else {
                MBAR_EXPECT_TX(fb, 16384u);
                BULK_G2S(ab, asrc, 16384u, fb);
            }
        }
        MBAR_WAIT(sb + (sA ? SM_FULL1 : SM_FULL0), (it >> 1) & 1);

        uint32_t Ab = sb + (sA ? SM_A1 : SM_A0);
        uint32_t Bb = sb + (sB ? SM_B1 : SM_B0);
        #pragma unroll
        for (int kk = 0; kk < 4; ++kk) {
            uint32_t kb = (uint32_t)(kk * 32 + lhalf * 16);   // k-bytes for this lane
            uint32_t ra[4][4], rbm[2][4];
            #pragma unroll
            for (int mf = 0; mf < 4; ++mf)
                LDSM_X4(ra[mf], Ab + aR + mf * 2048 + (kb ^ S));
            #pragma unroll
            for (int nf2 = 0; nf2 < 2; ++nf2)
                LDSM_X4(rbm[nf2], Bb + bR + nf2 * 2048 + (kb ^ S));
            #pragma unroll
            for (int mf = 0; mf < 4; ++mf)
                #pragma unroll
                for (int nf = 0; nf < 4; ++nf)
                    MMA_BF16(acc[mf][nf], ra[mf], rbm[nf >> 1][nf & 1], rbm[nf >> 1][(nf & 1) + 2]);
        }
        __syncthreads();

        if ((it & 15) == 15) {
            int dt = it >> 4;
            #pragma unroll
            for (int mf = 0; mf < 4; ++mf) {
                int r1 = wm * 64 + mf * 16 + (lane >> 2);
                const float* x1 = X + (size_t)(n0 + r1) * DIM;
                const float* x2 = x1 + 8 * DIM;
                float s1 = 0.f, s2 = 0.f;
                #pragma unroll
                for (int nf = 0; nf < 4; ++nf) {
                    int c0 = dt * 128 + wn * 32 + nf * 8 + (lane & 3) * 2;
                    float v0 = vsh[c0], v1 = vsh[c0 + 1];
                    s1 += x1[c0] * (v0 - 0.5f * acc[mf][nf][0]) + x1[c0 + 1] * (v1 - 0.5f * acc[mf][nf][1]);
                    s2 += x2[c0] * (v0 - 0.5f * acc[mf][nf][2]) + x2[c0 + 1] * (v1 - 0.5f * acc[mf][nf][3]);
                    acc[mf][nf][0] = acc[mf][nf][1] = acc[mf][nf][2] = acc[mf][nf][3] = 0.f;
                }
                scp[mf * 2 + 0] += s1;
                scp[mf * 2 + 1] += s2;
            }
        }
    }

    // reduce scp over the 4 lanes sharing each row (lane&3 group), then across n-warps via smem
    #pragma unroll
    for (int i = 0; i < 8; ++i) {
        float s = scp[i];
        s += __shfl_xor_sync(0xffffffffu, s, 1);
        s += __shfl_xor_sync(0xffffffffu, s, 2);
        scp[i] = s;
    }
    float* red = (float*)(smem + SM_RED);   // [4 wn][128 rows]
    if ((lane & 3) == 0) {
        int rsub = lane >> 2;
        #pragma unroll
        for (int mf = 0; mf < 4; ++mf) {
            red[wn * 128 + wm * 64 + mf * 16 + 0 + rsub] = scp[mf * 2 + 0];
            red[wn * 128 + wm * 64 + mf * 16 + 8 + rsub] = scp[mf * 2 + 1];
        }
    }
    __syncthreads();
    for (int r = tid; r < 128; r += 256) {
        float s = red[r] + red[128 + r] + red[256 + r] + red[384 + r];
        out[(size_t)(n0 + r) * NCLS + c] = g_const[c] + s;
    }
}

// ================= launch =================
extern "C" void kernel_launch(void* const* d_in, const int* in_sizes, int n_in,
                              void* d_out, int out_size) {
    const float* X    = (const float*)d_in[0];   // [2048, 512]
    const float* muK  = (const float*)d_in[1];   // [100, 512]
    const float* SigK = (const float*)d_in[2];   // [100, 512, 512]
    const float* Sig  = (const float*)d_in[3];   // [512, 512]
    const float* cK   = (const float*)d_in[4];   // [100]
    float* out = (float*)d_out;                  // [2048, 100]

    cudaFuncSetAttribute(quad_mma_kernel, cudaFuncAttributeMaxDynamicSharedMemorySize, SM_TOTAL_Q);

    build_kernel<<<dim3(DIM, NCLS), 128>>>(SigK, Sig);
    frob_kernel<<<NCLS, 256>>>(SigK, Sig);
    split_x_kernel<<<dim3(16, 8), 256>>>(X);
    invert_kernel<<<NCLS, 256>>>();
    vgamma_kernel<<<NCLS, 512>>>(muK, cK);
    split_l_kernel<<<dim3(NCLS, 8), 256>>>();
    quad_mma_kernel<<<dim3(16, NCLS), 256, SM_TOTAL_Q>>>(X, out);
}